// round 11
// baseline (speedup 1.0000x reference)
#include <cuda_runtime.h>
#include <cstdint>

// ItemEncoder R11: bulk-async ring, 8-token stages, 16 warps,
// XOR-rotated selection-free butterfly transpose-reduce.
//   out[t,:] = M[ids[t],:] @ W^T + b ; 12800 tokens, D=2000, O=8.
//
//  - 1 CTA / SM, 512 threads. Warp w: token-group g=w>>3 (4 of the 8
//    stage tokens), quad-partition p=w&7 (quads [64p, 64p+64)).
//  - Warp 15 lane 0 doubles as producer: issues 8 cp.async.bulk rows for
//    stage k+2 at the top of iter k (slot freed by iter k-1's bar).
//    NBUF=3 x 64000 B ring; __syncthreads is the empty-barrier.
//  - XOR trick: lane l loads token row (t'^ (l>>3)) and W row (o'^(l&7)),
//    so acc slot j=t'*8+o' holds value j^l. Butterfly then needs NO
//    selects: cur[j] += shfl_xor(cur[j+off], off). 31 shfl + 31 add.
//  - W via __ldg per stage (L1-resident 64 KB); regs stay ~100 (512 thr
//    cap is 128; W-in-regs spilled in R8).

static constexpr int NTOK  = 12800;
static constexpr int D     = 2000;
static constexpr int ROWB  = D * 4;          // 8000 B
static constexpr int QPR   = D / 4;          // 500 quads/row
static constexpr int STOK  = 8;
static constexpr int NSTG  = NTOK / STOK;    // 1600
static constexpr int NTHR  = 512;
static constexpr int NBUF  = 3;
static constexpr int LOOKAHEAD = NBUF - 1;   // 2 stages (128 KB) in flight
static constexpr int STAGEB  = STOK * ROWB;  // 64000
static constexpr int BSTRIDE = STAGEB + 256; // zeroed pad for quads 500..511
static constexpr int SM_RED  = NBUF * BSTRIDE;       // 192768
static constexpr int SM_MBAR = SM_RED + 4096;        // red: 2 x 512 floats
static constexpr int SM_TOT  = SM_MBAR + NBUF * 8;   // 3 full-mbarriers

__device__ __forceinline__ void ffma2(unsigned long long &acc,
                                      unsigned long long a,
                                      unsigned long long b) {
    asm("fma.rn.f32x2 %0, %1, %2, %0;" : "+l"(acc) : "l"(a), "l"(b));
}
__device__ __forceinline__ unsigned long long fmul2(unsigned long long a,
                                                    unsigned long long b) {
    unsigned long long r;
    asm("mul.rn.f32x2 %0, %1, %2;" : "=l"(r) : "l"(a), "l"(b));
    return r;
}
__device__ __forceinline__ void mbar_init(uint32_t a, uint32_t cnt) {
    asm volatile("mbarrier.init.shared.b64 [%0], %1;" :: "r"(a), "r"(cnt) : "memory");
}
__device__ __forceinline__ void mbar_expect_tx(uint32_t a, uint32_t bytes) {
    asm volatile("mbarrier.arrive.expect_tx.shared.b64 _, [%0], %1;"
                 :: "r"(a), "r"(bytes) : "memory");
}
__device__ __forceinline__ void mbar_wait(uint32_t a, uint32_t parity) {
    asm volatile(
        "{\n\t.reg .pred P;\n\t"
        "WL_%=:\n\t"
        "mbarrier.try_wait.parity.acquire.cta.shared::cta.b64 P, [%0], %1, 0x989680;\n\t"
        "@P bra WD_%=;\n\t"
        "bra WL_%=;\n\t"
        "WD_%=:\n\t}"
        :: "r"(a), "r"(parity) : "memory");
}
__device__ __forceinline__ void bulk_cp(uint32_t smem_dst, const void* gmem_src,
                                        uint32_t bytes, uint32_t mbar) {
    asm volatile(
        "cp.async.bulk.shared::cta.global.mbarrier::complete_tx::bytes "
        "[%0], [%1], %2, [%3];"
        :: "r"(smem_dst), "l"(gmem_src), "r"(bytes), "r"(mbar) : "memory");
}

__global__ void __launch_bounds__(NTHR, 1)
gather_proj_r11(const int*   __restrict__ ids,
                const float* __restrict__ M,
                const float* __restrict__ W,
                const float* __restrict__ bias,
                float*       __restrict__ out)
{
    extern __shared__ char smem[];
    const uint32_t smem_u32 = (uint32_t)__cvta_generic_to_shared(smem);
    const int tid  = threadIdx.x;
    const int lane = tid & 31;
    const int wid  = tid >> 5;
    const int g    = wid >> 3;          // token-group (0/1): tokens g*4..g*4+3
    const int p    = wid & 7;           // quad-partition: quads [64p, 64p+64)
    const int lt   = lane >> 3;         // token-XOR rotation (2 bits)
    const int lo   = lane & 7;          // output-XOR rotation (3 bits)

    const int gridn  = gridDim.x;
    const int s0     = blockIdx.x;
    const int nLocal = (NSTG - s0 + gridn - 1) / gridn;

    auto fullb = [&](int s) -> uint32_t { return smem_u32 + SM_MBAR + s * 8; };

    // ---- init: mbarriers + zero ring pads ----
    if (tid == 0) {
#pragma unroll
        for (int s = 0; s < NBUF; ++s) mbar_init(fullb(s), 1);
    }
    if (tid < NBUF * 16) {              // 3 x 256 B pads (quads 500..511, token 7)
        int b = tid >> 4, qq = tid & 15;
        *(float4*)(smem + b * BSTRIDE + STAGEB + qq * 16) =
            make_float4(0.f, 0.f, 0.f, 0.f);
    }
    const float bval = __ldg(bias + (lane & 7));
    const char* Mb = (const char*)M;
    const ulonglong2* Wq = (const ulonglong2*)W;

    __syncthreads();                    // mbarriers + pads visible

    // ---- producer (warp 15 lane 0): prologue 2 stages, then pipelined ids ----
    const bool isProd = (wid == 15) && (lane == 0);
    int4 nid0, nid1;                    // ids (8) for next stage to issue
    if (isProd) {
#pragma unroll
        for (int j = 0; j < LOOKAHEAD; ++j) {
            if (j < nLocal) {
                const int st = s0 + j * gridn;
                const int4 a0 = __ldg((const int4*)ids + st * 2);
                const int4 a1 = __ldg((const int4*)ids + st * 2 + 1);
                const int js = j % NBUF;
                const uint32_t dst = smem_u32 + js * BSTRIDE;
                mbar_expect_tx(fullb(js), STAGEB);
                bulk_cp(dst,            Mb + (size_t)a0.x * ROWB, ROWB, fullb(js));
                bulk_cp(dst + 1 * ROWB, Mb + (size_t)a0.y * ROWB, ROWB, fullb(js));
                bulk_cp(dst + 2 * ROWB, Mb + (size_t)a0.z * ROWB, ROWB, fullb(js));
                bulk_cp(dst + 3 * ROWB, Mb + (size_t)a0.w * ROWB, ROWB, fullb(js));
                bulk_cp(dst + 4 * ROWB, Mb + (size_t)a1.x * ROWB, ROWB, fullb(js));
                bulk_cp(dst + 5 * ROWB, Mb + (size_t)a1.y * ROWB, ROWB, fullb(js));
                bulk_cp(dst + 6 * ROWB, Mb + (size_t)a1.z * ROWB, ROWB, fullb(js));
                bulk_cp(dst + 7 * ROWB, Mb + (size_t)a1.w * ROWB, ROWB, fullb(js));
            }
        }
        if (LOOKAHEAD < nLocal) {       // preload ids for stage LOOKAHEAD
            const int st = s0 + LOOKAHEAD * gridn;
            nid0 = __ldg((const int4*)ids + st * 2);
            nid1 = __ldg((const int4*)ids + st * 2 + 1);
        }
    }

    float* red = (float*)(smem + SM_RED);
    int slot = 0, phase = 0;

    for (int k = 0; k < nLocal; ++k) {
        // ---- producer: issue stage k+2 (slot freed by iter k-1's bar) ----
        if (isProd) {
            const int j = k + LOOKAHEAD;
            if (j < nLocal) {
                const int js = j % NBUF;
                const uint32_t dst = smem_u32 + js * BSTRIDE;
                mbar_expect_tx(fullb(js), STAGEB);
                bulk_cp(dst,            Mb + (size_t)nid0.x * ROWB, ROWB, fullb(js));
                bulk_cp(dst + 1 * ROWB, Mb + (size_t)nid0.y * ROWB, ROWB, fullb(js));
                bulk_cp(dst + 2 * ROWB, Mb + (size_t)nid0.z * ROWB, ROWB, fullb(js));
                bulk_cp(dst + 3 * ROWB, Mb + (size_t)nid0.w * ROWB, ROWB, fullb(js));
                bulk_cp(dst + 4 * ROWB, Mb + (size_t)nid1.x * ROWB, ROWB, fullb(js));
                bulk_cp(dst + 5 * ROWB, Mb + (size_t)nid1.y * ROWB, ROWB, fullb(js));
                bulk_cp(dst + 6 * ROWB, Mb + (size_t)nid1.z * ROWB, ROWB, fullb(js));
                bulk_cp(dst + 7 * ROWB, Mb + (size_t)nid1.w * ROWB, ROWB, fullb(js));
                if (j + 1 < nLocal) {   // ids pipelined one stage ahead
                    const int st = s0 + (j + 1) * gridn;
                    nid0 = __ldg((const int4*)ids + st * 2);
                    nid1 = __ldg((const int4*)ids + st * 2 + 1);
                }
            }
        }

        // ---- wait for stage k, compute ----
        mbar_wait(fullb(slot), phase);
        const char* buf = smem + slot * BSTRIDE + g * 4 * ROWB;

        unsigned long long acc[4][8];
#pragma unroll
        for (int it = 0; it < 2; ++it) {
            const int  q   = p * 64 + it * 32 + lane;   // 480..511 OOB for p=7,it=1
            const bool inb = (q < QPR);
            // token rows XOR-rotated by lt: slot t' holds token (t'^lt)
            ulonglong2 v[4];
#pragma unroll
            for (int t = 0; t < 4; ++t)
                v[t] = *(const ulonglong2*)(buf + (t ^ lt) * ROWB + q * 16);
#pragma unroll
            for (int o = 0; o < 8; ++o) {
                // W rows XOR-rotated by lo: slot o' holds output (o'^lo); OOB -> 0
                ulonglong2 wv = inb ? __ldg(Wq + (o ^ lo) * QPR + q)
                                    : make_ulonglong2(0ull, 0ull);
#pragma unroll
                for (int t = 0; t < 4; ++t) {
                    if (it == 0) {
                        acc[t][o] = fmul2(v[t].x, wv.x);
                        ffma2(acc[t][o], v[t].y, wv.y);
                    } else {
                        ffma2(acc[t][o], v[t].x, wv.x);
                        ffma2(acc[t][o], v[t].y, wv.y);
                    }
                }
            }
        }

        // ---- collapse f32x2 -> 32 scalars; slot j holds value j^lane ----
        float cur[32];
#pragma unroll
        for (int t = 0; t < 4; ++t)
#pragma unroll
            for (int o = 0; o < 8; ++o) {
                const unsigned long long a = acc[t][o];
                cur[t * 8 + o] = __uint_as_float((unsigned)a) +
                                 __uint_as_float((unsigned)(a >> 32));
            }

        // ---- selection-free butterfly: 31 shfl + 31 add ----
#pragma unroll
        for (int off = 16; off >= 1; off >>= 1) {
#pragma unroll
            for (int j = 0; j < off; ++j)
                cur[j] += __shfl_xor_sync(0xffffffffu, cur[j + off], off);
        }
        // lane l: cur[0] = full partial of value l (token g*4+(l>>3), out l&7)

        float* redk = red + (k & 1) * 512;
        redk[g * 256 + p * 32 + lane] = cur[0];
        __syncthreads();                 // red visible; slot k fully read

        if (p == 0) {                    // warps 0 and 8 finalize their group
            float s = bval;
#pragma unroll
            for (int pp = 0; pp < 8; ++pp) s += redk[g * 256 + pp * 32 + lane];
            out[(size_t)(s0 + k * gridn) * 64 + g * 32 + lane] = s;
        }

        if (++slot == NBUF) { slot = 0; phase ^= 1; }
    }
}

extern "C" void kernel_launch(void* const* d_in, const int* in_sizes, int n_in,
                              void* d_out, int out_size) {
    const int*   ids  = (const int*)  d_in[0];
    const float* M    = (const float*)d_in[1];
    const float* W    = (const float*)d_in[2];
    const float* bias = (const float*)d_in[3];
    float*       out  = (float*)d_out;

    cudaFuncSetAttribute(gather_proj_r11,
                         cudaFuncAttributeMaxDynamicSharedMemorySize, SM_TOT);

    int nsm = 148;
    cudaDeviceGetAttribute(&nsm, cudaDevAttrMultiProcessorCount, 0);

    gather_proj_r11<<<nsm, NTHR, SM_TOT>>>(ids, M, W, bias, out);
}

// round 12
// speedup vs baseline: 2.3267x; 2.3267x over previous
#include <cuda_runtime.h>
#include <cstdint>

// ItemEncoder R12: R4 architecture (TMA-bulk 6-slot ring, 8 consumer warps,
// W in registers, producer warp) + two fixes aimed at R4's measured
// 2050-cyc stage cadence:
//   (a) XOR-rotated W REGISTERS (rotation applied once at load; streamed
//       loads stay coalesced, unlike R11) + token-rotated LDS
//       -> selection-free butterfly: 31 shfl + 31 add, zero SELs.
//   (b) empty[slot] mbar count = 1, arrived by tid0 after the consumer
//       named barrier (replaces R4's 256-thread arrive storm).
//   (c) producer ids LDG pipelined one stage ahead.
//   out[t,:] = M[ids[t],:] @ W^T + b ; 12800 tokens, D=2000, O=8.

static constexpr int NTOK  = 12800;
static constexpr int D     = 2000;
static constexpr int ROWB  = D * 4;          // 8000 B
static constexpr int QPR   = D / 4;          // 500
static constexpr int STOK  = 4;
static constexpr int NSTG  = NTOK / STOK;    // 3200
static constexpr int NTHR  = 288;
static constexpr int NCONS = 256;
static constexpr int NBUF  = 6;
static constexpr int STAGEB  = STOK * ROWB;  // 32000
static constexpr int BSTRIDE = 32256;        // +256 B zeroed pad (quads 500..511)
static constexpr int SM_RED  = NBUF * BSTRIDE;       // 193536; red 2 x 1024 B
static constexpr int SM_MBAR = SM_RED + 2048;
static constexpr int SM_TOT  = SM_MBAR + NBUF * 16;  // full+empty per slot

__device__ __forceinline__ void ffma2(unsigned long long &acc,
                                      unsigned long long a,
                                      unsigned long long b) {
    asm("fma.rn.f32x2 %0, %1, %2, %0;" : "+l"(acc) : "l"(a), "l"(b));
}
__device__ __forceinline__ void mbar_init(uint32_t a, uint32_t cnt) {
    asm volatile("mbarrier.init.shared.b64 [%0], %1;" :: "r"(a), "r"(cnt) : "memory");
}
__device__ __forceinline__ void mbar_expect_tx(uint32_t a, uint32_t bytes) {
    asm volatile("mbarrier.arrive.expect_tx.shared.b64 _, [%0], %1;"
                 :: "r"(a), "r"(bytes) : "memory");
}
__device__ __forceinline__ void mbar_arrive(uint32_t a) {
    asm volatile("mbarrier.arrive.shared.b64 _, [%0];" :: "r"(a) : "memory");
}
__device__ __forceinline__ void mbar_wait(uint32_t a, uint32_t parity) {
    asm volatile(
        "{\n\t.reg .pred P;\n\t"
        "WL_%=:\n\t"
        "mbarrier.try_wait.parity.acquire.cta.shared::cta.b64 P, [%0], %1, 0x989680;\n\t"
        "@P bra WD_%=;\n\t"
        "bra WL_%=;\n\t"
        "WD_%=:\n\t}"
        :: "r"(a), "r"(parity) : "memory");
}
__device__ __forceinline__ void bulk_cp(uint32_t smem_dst, const void* gmem_src,
                                        uint32_t bytes, uint32_t mbar) {
    asm volatile(
        "cp.async.bulk.shared::cta.global.mbarrier::complete_tx::bytes "
        "[%0], [%1], %2, [%3];"
        :: "r"(smem_dst), "l"(gmem_src), "r"(bytes), "r"(mbar) : "memory");
}
__device__ __forceinline__ void bar_cons() {     // consumers only (256 threads)
    asm volatile("bar.sync 1, %0;" :: "n"(NCONS) : "memory");
}

__global__ void __launch_bounds__(NTHR, 1)
gather_proj_r12(const int*   __restrict__ ids,
                const float* __restrict__ M,
                const float* __restrict__ W,
                const float* __restrict__ bias,
                float*       __restrict__ out)
{
    extern __shared__ char smem[];
    const uint32_t smem_u32 = (uint32_t)__cvta_generic_to_shared(smem);
    const int tid  = threadIdx.x;
    const int lane = tid & 31;
    const int wid  = tid >> 5;
    const int lt   = lane >> 3;   // token rotation (2 bits)
    const int lo   = lane & 7;    // output rotation (3 bits)

    const int gridn  = gridDim.x;
    const int s0     = blockIdx.x;
    const int nLocal = (NSTG - s0 + gridn - 1) / gridn;

    auto fullb  = [&](int s) -> uint32_t { return smem_u32 + SM_MBAR + s * 16; };
    auto emptyb = [&](int s) -> uint32_t { return smem_u32 + SM_MBAR + s * 16 + 8; };

    // ---- init: mbarriers + zero ring pads ----
    if (tid == 0) {
#pragma unroll
        for (int s = 0; s < NBUF; ++s) {
            mbar_init(fullb(s), 1);    // armed by producer expect_tx
            mbar_init(emptyb(s), 1);   // single arrive by tid0 after group bar
        }
    }
    if (tid < NBUF * 16) {             // zero 6 x 256 B pads (quads 500..511)
        int b = tid >> 4, qq = tid & 15;
        *(float4*)(smem + b * BSTRIDE + STAGEB + qq * 16) =
            make_float4(0.f, 0.f, 0.f, 0.f);
    }
    __syncthreads();                   // mbarriers + pads visible to all

    if (wid == 8) {
        // ================= producer (lane 0) =================
        if (lane == 0) {
            const char* Mb = (const char*)M;
            int phase = 1;             // fresh empty barriers: first waits pass
            int4 nid = __ldg((const int4*)ids + s0);   // stage 0 ids
            for (int k = 0; k < nLocal; ++k) {
                const int slot = k % NBUF;
                mbar_wait(emptyb(slot), phase);
                const uint32_t dst = smem_u32 + slot * BSTRIDE;
                mbar_expect_tx(fullb(slot), STAGEB);
                bulk_cp(dst,            Mb + (size_t)nid.x * ROWB, ROWB, fullb(slot));
                bulk_cp(dst + ROWB,     Mb + (size_t)nid.y * ROWB, ROWB, fullb(slot));
                bulk_cp(dst + 2 * ROWB, Mb + (size_t)nid.z * ROWB, ROWB, fullb(slot));
                bulk_cp(dst + 3 * ROWB, Mb + (size_t)nid.w * ROWB, ROWB, fullb(slot));
                if (k + 1 < nLocal)    // ids pipelined one stage ahead
                    nid = __ldg((const int4*)ids + (s0 + (k + 1) * gridn));
                if (slot == NBUF - 1) phase ^= 1;
            }
        }
        return;
    }

    // ================= consumers (warps 0-7) =================
    const float bval = __ldg(bias + (lane & 7));

    // W into registers, XOR-rotated by lo: reg slot o holds W row (o^lo).
    // Uncoalesced, but executed exactly once. Zeroed for OOB quads.
    ulonglong2 w[2][8];
#pragma unroll
    for (int it = 0; it < 2; ++it) {
        const int q = wid * 64 + it * 32 + lane;
#pragma unroll
        for (int o = 0; o < 8; ++o) {
            if (q < QPR) w[it][o] = __ldg((const ulonglong2*)W + (o ^ lo) * QPR + q);
            else         w[it][o] = make_ulonglong2(0ull, 0ull);
        }
    }

    float* red = (float*)(smem + SM_RED);
    int slot = 0, phase = 0;

    for (int k = 0; k < nLocal; ++k) {
        mbar_wait(fullb(slot), phase);
        const char* buf = smem + slot * BSTRIDE;

        unsigned long long acc[4][8];
#pragma unroll
        for (int t = 0; t < 4; ++t)
#pragma unroll
            for (int o = 0; o < 8; ++o) acc[t][o] = 0ull;

#pragma unroll
        for (int it = 0; it < 2; ++it) {
            const int q = wid * 64 + it * 32 + lane;   // 500..511 hit pad, w=0
            // token rows XOR-rotated by lt: v slot t holds token (t^lt)
            ulonglong2 v[4];
#pragma unroll
            for (int t = 0; t < 4; ++t)
                v[t] = *(const ulonglong2*)(buf + (t ^ lt) * ROWB + q * 16);
#pragma unroll
            for (int t = 0; t < 4; ++t)
#pragma unroll
                for (int o = 0; o < 8; ++o) {
                    ffma2(acc[t][o], v[t].x, w[it][o].x);
                    ffma2(acc[t][o], v[t].y, w[it][o].y);
                }
        }
        // acc slot j = t*8+o holds partial of value (t^lt)*8+(o^lo) = j^lane

        // ---- collapse f32x2 halves -> 32 scalars ----
        float cur[32];
#pragma unroll
        for (int t = 0; t < 4; ++t)
#pragma unroll
            for (int o = 0; o < 8; ++o) {
                const unsigned long long a = acc[t][o];
                cur[t * 8 + o] = __uint_as_float((unsigned)a) +
                                 __uint_as_float((unsigned)(a >> 32));
            }

        // ---- selection-free butterfly: 31 shfl + 31 add ----
#pragma unroll
        for (int off = 16; off >= 1; off >>= 1) {
#pragma unroll
            for (int j = 0; j < off; ++j)
                cur[j] += __shfl_xor_sync(0xffffffffu, cur[j + off], off);
        }
        // lane l: cur[0] = this warp's total of value l (token l>>3, out l&7)

        float* redk = red + (k & 1) * 256;
        redk[wid * 32 + lane] = cur[0];
        bar_cons();                    // red visible; ALL consumer buf reads done
        if (tid == 0) mbar_arrive(emptyb(slot));   // single release arrive

        if (wid == 0) {
            float s = bval;
#pragma unroll
            for (int w8 = 0; w8 < 8; ++w8) s += redk[w8 * 32 + lane];
            out[(size_t)(s0 + k * gridn) * 32 + lane] = s;
        }

        if (++slot == NBUF) { slot = 0; phase ^= 1; }
    }
}

extern "C" void kernel_launch(void* const* d_in, const int* in_sizes, int n_in,
                              void* d_out, int out_size) {
    const int*   ids  = (const int*)  d_in[0];
    const float* M    = (const float*)d_in[1];
    const float* W    = (const float*)d_in[2];
    const float* bias = (const float*)d_in[3];
    float*       out  = (float*)d_out;

    cudaFuncSetAttribute(gather_proj_r12,
                         cudaFuncAttributeMaxDynamicSharedMemorySize, SM_TOT);

    int nsm = 148;
    cudaDeviceGetAttribute(&nsm, cudaDevAttrMultiProcessorCount, 0);

    gather_proj_r12<<<nsm, NTHR, SM_TOT>>>(ids, M, W, bias, out);
}